// round 5
// baseline (speedup 1.0000x reference)
#include <cuda_runtime.h>
#include <cstdint>

// Problem constants
#define RANK   64
#define NTOK   8192
#define KDIM   4096   // A1*B1 (GEMM contraction dim)
#define NDIM   4096   // A2*B2 (GEMM output cols)

// GEMM tiling
#define BM 128
#define BN 256
#define BK 32
#define NTHREADS 256
#define AS_STRIDE 36                       // 32 + 4 pad -> bank = (4m + k) % 32, conflict-free frag loads
#define AS_SIZE   (BM * AS_STRIDE)         // 4608 floats per stage
#define BS_SIZE   (2 * 32 * 32 * 4)        // 8192 floats per stage (fragment-ordered W tile)
#define SMEM_BYTES (2 * (AS_SIZE + BS_SIZE) * 4)  // 102400

// Scratch (static __device__ globals are the sanctioned no-alloc scratch)
__device__ float g_X[(size_t)NTOK * KDIM];     // tf32-rounded x (128 MB)
__device__ float g_W[(size_t)KDIM * NDIM];     // W in B-fragment order (64 MB)

__device__ __forceinline__ uint32_t f32_to_tf32(float f) {
    uint32_t r;
    asm("cvt.rna.tf32.f32 %0, %1;" : "=r"(r) : "f"(f));
    return r;
}

__device__ __forceinline__ void cp_async16(float* smem_dst, const float* gmem_src) {
    uint32_t s = (uint32_t)__cvta_generic_to_shared(smem_dst);
    asm volatile("cp.async.cg.shared.global [%0], [%1], 16;\n" :: "r"(s), "l"(gmem_src));
}

__device__ __forceinline__ void mma_tf32(float* d, const uint32_t* a, uint32_t b0, uint32_t b1) {
    asm volatile(
        "mma.sync.aligned.m16n8k8.row.col.f32.tf32.tf32.f32 "
        "{%0,%1,%2,%3}, {%4,%5,%6,%7}, {%8,%9}, {%0,%1,%2,%3};\n"
        : "+f"(d[0]), "+f"(d[1]), "+f"(d[2]), "+f"(d[3])
        : "r"(a[0]), "r"(a[1]), "r"(a[2]), "r"(a[3]), "r"(b0), "r"(b1));
}

// ---------------------------------------------------------------------------
// Kernel 1: round x to tf32 (rna) into g_X. One float4 per thread.
// ---------------------------------------------------------------------------
__global__ void cvt_x_kernel(const float* __restrict__ x) {
    int i = blockIdx.x * blockDim.x + threadIdx.x;   // float4 index, exact grid
    float4 v = ((const float4*)x)[i];
    uint4 o;
    o.x = f32_to_tf32(v.x);
    o.y = f32_to_tf32(v.y);
    o.z = f32_to_tf32(v.z);
    o.w = f32_to_tf32(v.w);
    ((uint4*)g_X)[i] = o;
}

// ---------------------------------------------------------------------------
// Kernel 2: build W[K][n] = sum_r a[r,i,j]*b[r,kk,l]  (K = i*64+kk, n = j*64+l),
// rounded to tf32, stored in B-FRAGMENT order for mma.m16n8k8:
//   g_W[nb][k16][nsG][lane][q], value = W[k16*16 + c + 4q][nb*256 + nsG*8 + g]
//   where lane = g*4 + c. One CTA per W row K; 4x4 register tile per thread.
// ---------------------------------------------------------------------------
__global__ void __launch_bounds__(256) build_w_kernel(const float* __restrict__ a,
                                                      const float* __restrict__ b) {
    __shared__ float sA[64 * 64];   // a[r][j] for fixed i
    __shared__ float sB[64 * 64];   // b[r][l] for fixed kk
    int K  = blockIdx.x;            // 0..4095
    int i  = K >> 6, kk = K & 63;
    int tid = threadIdx.x;

    for (int idx = tid; idx < 4096; idx += 256) {
        int r = idx >> 6, col = idx & 63;
        sA[idx] = a[r * 4096 + i  * 64 + col];
        sB[idx] = b[r * 4096 + kk * 64 + col];
    }
    __syncthreads();

    int tj = tid >> 4, tl = tid & 15;
    float acc[4][4];
    #pragma unroll
    for (int jj = 0; jj < 4; jj++)
        #pragma unroll
        for (int ll = 0; ll < 4; ll++) acc[jj][ll] = 0.0f;

    const float4* sA4 = (const float4*)sA;
    const float4* sB4 = (const float4*)sB;
    #pragma unroll 8
    for (int r = 0; r < 64; r++) {
        float4 av = sA4[r * 16 + tj];
        float4 bv = sB4[r * 16 + tl];
        float aj[4] = {av.x, av.y, av.z, av.w};
        float bl[4] = {bv.x, bv.y, bv.z, bv.w};
        #pragma unroll
        for (int jj = 0; jj < 4; jj++)
            #pragma unroll
            for (int ll = 0; ll < 4; ll++)
                acc[jj][ll] = fmaf(aj[jj], bl[ll], acc[jj][ll]);
    }

    int k16 = K >> 4, c = K & 3, q = (K >> 2) & 3;
    #pragma unroll
    for (int jj = 0; jj < 4; jj++) {
        int j = tj * 4 + jj;
        #pragma unroll
        for (int ll = 0; ll < 4; ll++) {
            int l  = tl * 4 + ll;
            int n  = j * 64 + l;
            int nb = n >> 8, nsG = (n >> 3) & 31, g = n & 7;
            int lane = (g << 2) | c;
            size_t idx = ((((size_t)nb * 256 + k16) * 32 + nsG) * 32 + lane) * 4 + q;
            g_W[idx] = __uint_as_float(f32_to_tf32(acc[jj][ll]));
        }
    }
}

// ---------------------------------------------------------------------------
// Kernel 3: GEMM out[8192,4096] = g_X @ W + bias, tf32 mma, fp32 accum.
// BM=128, BN=256, BK=32; 8 warps in 2(m) x 4(n) grid, warp tile 64x64;
// double-buffered cp.async pipeline.
// ---------------------------------------------------------------------------
__device__ __forceinline__ void prefetch_tiles(int ki, float* As, float* Bs,
                                               const float* Xg, const float* Wg, int tid) {
    const float* srcA = Xg + ki * 32;
    #pragma unroll
    for (int it = 0; it < 4; it++) {
        int p = tid + it * 256;          // 1024 float4 positions: 128 rows x 8 cols
        int row = p >> 3, c4 = p & 7;
        cp_async16(As + row * AS_STRIDE + c4 * 4, srcA + row * KDIM + c4 * 4);
    }
    const float* srcB = Wg + ki * 8192;  // 32 KB contiguous fragment-ordered chunk
    #pragma unroll
    for (int it = 0; it < 8; it++) {
        int p = tid + it * 256;
        cp_async16(Bs + p * 4, srcB + p * 4);
    }
}

__global__ void __launch_bounds__(256, 1)
gemm_kernel(const float* __restrict__ bias, float* __restrict__ out) {
    extern __shared__ float smem[];
    float* AsBase = smem;                 // [2][AS_SIZE]
    float* BsBase = smem + 2 * AS_SIZE;   // [2][BS_SIZE]

    int tid  = threadIdx.x;
    int nb   = blockIdx.x;   // 0..15
    int mb   = blockIdx.y;   // 0..63
    int wid  = tid >> 5, lane = tid & 31;
    int wm   = wid >> 2;     // 0..1
    int wn   = wid & 3;      // 0..3
    int g    = lane >> 2, c = lane & 3;

    const float* Xg = g_X + (size_t)mb * 128 * KDIM;
    const float* Wg = g_W + (size_t)nb * (256 * 32 * 32 * 4);

    float acc[4][8][4];
    #pragma unroll
    for (int mt = 0; mt < 4; mt++)
        #pragma unroll
        for (int ns = 0; ns < 8; ns++)
            #pragma unroll
            for (int r = 0; r < 4; r++) acc[mt][ns][r] = 0.0f;

    prefetch_tiles(0, AsBase, BsBase, Xg, Wg, tid);
    asm volatile("cp.async.commit_group;\n");

    const int NIT = KDIM / BK;   // 128
    for (int ki = 0; ki < NIT; ki++) {
        int buf = ki & 1;
        if (ki + 1 < NIT) {
            prefetch_tiles(ki + 1, AsBase + (buf ^ 1) * AS_SIZE,
                           BsBase + (buf ^ 1) * BS_SIZE, Xg, Wg, tid);
            asm volatile("cp.async.commit_group;\n");
            asm volatile("cp.async.wait_group 1;\n");
        } else {
            asm volatile("cp.async.wait_group 0;\n");
        }
        __syncthreads();

        const float* A_ = AsBase + buf * AS_SIZE;
        const float* B_ = BsBase + buf * BS_SIZE;

        #pragma unroll
        for (int p = 0; p < 2; p++) {    // k-step pairs (covers 2x k8)
            float4 bv[8];
            #pragma unroll
            for (int ns = 0; ns < 8; ns++)
                bv[ns] = *(const float4*)(B_ + ((p * 32 + wn * 8 + ns) * 32 + lane) * 4);

            #pragma unroll
            for (int h = 0; h < 2; h++) {
                int s = p * 2 + h;       // k-step within BK (0..3)
                uint32_t afr[4][4];
                #pragma unroll
                for (int mt = 0; mt < 4; mt++) {
                    const float* ap = A_ + (wm * 64 + mt * 16 + g) * AS_STRIDE + s * 8 + c;
                    afr[mt][0] = __float_as_uint(ap[0]);
                    afr[mt][1] = __float_as_uint(ap[8 * AS_STRIDE]);
                    afr[mt][2] = __float_as_uint(ap[4]);
                    afr[mt][3] = __float_as_uint(ap[8 * AS_STRIDE + 4]);
                }
                #pragma unroll
                for (int mt = 0; mt < 4; mt++) {
                    #pragma unroll
                    for (int ns = 0; ns < 8; ns++) {
                        uint32_t b0 = h ? __float_as_uint(bv[ns].z) : __float_as_uint(bv[ns].x);
                        uint32_t b1 = h ? __float_as_uint(bv[ns].w) : __float_as_uint(bv[ns].y);
                        mma_tf32(acc[mt][ns], afr[mt], b0, b1);
                    }
                }
            }
        }
        __syncthreads();
    }

    // Epilogue: add bias, write fp32
    int nbase = nb * 256 + wn * 64;
    int mbase = mb * 128 + wm * 64;
    #pragma unroll
    for (int mt = 0; mt < 4; mt++) {
        int r0 = mbase + mt * 16 + g;
        #pragma unroll
        for (int ns = 0; ns < 8; ns++) {
            int col = nbase + ns * 8 + 2 * c;
            float b0 = bias[col];
            float b1 = bias[col + 1];
            float2 v0 = make_float2(acc[mt][ns][0] + b0, acc[mt][ns][1] + b1);
            float2 v1 = make_float2(acc[mt][ns][2] + b0, acc[mt][ns][3] + b1);
            *(float2*)(out + (size_t)r0 * NDIM + col)       = v0;
            *(float2*)(out + (size_t)(r0 + 8) * NDIM + col) = v1;
        }
    }
}

// ---------------------------------------------------------------------------
extern "C" void kernel_launch(void* const* d_in, const int* in_sizes, int n_in,
                              void* d_out, int out_size) {
    // Identify inputs by element count (robust to ordering): x=33554432,
    // a and b = 262144 (in order of appearance), bias = 4096.
    const float *x = nullptr, *a = nullptr, *b = nullptr, *bias = nullptr;
    for (int idx = 0; idx < n_in; ++idx) {
        int s = in_sizes[idx];
        if (s == NTOK * KDIM && !x) x = (const float*)d_in[idx];
        else if (s == RANK * 64 * 64) { if (!a) a = (const float*)d_in[idx]; else if (!b) b = (const float*)d_in[idx]; }
        else if (s == NDIM && !bias) bias = (const float*)d_in[idx];
    }
    if (!x)    x    = (const float*)d_in[0];
    if (!a)    a    = (const float*)d_in[1];
    if (!b)    b    = (const float*)d_in[2];
    if (!bias) bias = (const float*)d_in[3];
    float* out = (float*)d_out;

    cvt_x_kernel<<<(NTOK * KDIM) / 4 / 256, 256>>>(x);
    build_w_kernel<<<KDIM, 256>>>(a, b);

    cudaFuncSetAttribute(gemm_kernel, cudaFuncAttributeMaxDynamicSharedMemorySize, SMEM_BYTES);
    dim3 grid(NDIM / BN, NTOK / BM);   // (16, 64)
    gemm_kernel<<<grid, NTHREADS, SMEM_BYTES>>>(bias, out);
}